// round 2
// baseline (speedup 1.0000x reference)
#include <cuda_runtime.h>

// Problem constants
#define BB 4
#define SS 2048
#define HH 16
#define DD 1024
#define DK 64
#define MTOT (BB * SS)          // 8192 rows for the projections

// Scratch (device globals — no allocation allowed)
__device__ float g_Q[BB * HH * SS * DK];   // [b,h,s,k]
__device__ float g_K[BB * HH * SS * DK];
__device__ float g_V[BB * HH * SS * DK];
__device__ float g_Z[BB * SS * DD];        // concat-heads layout [b,s,h*DK+k]

// ---------------------------------------------------------------------------
// Tiled fp32 GEMM: C = A[M,K] * W[N,K]^T + bias[N]
// MODE 0: C[m*N + n]            (plain row-major, used for output projection)
// MODE 1: C[((b*H+h)*S+s)*DK+k] (b=m/S, s=m%S, h=n/DK, k=n%DK) for Q/K/V
// Tiles: BM=BN=64, BK=16, 256 threads, each thread computes 4x4.
// ---------------------------------------------------------------------------
template <int MODE>
__global__ __launch_bounds__(256)
void gemm64(const float* __restrict__ A, const float* __restrict__ W,
            const float* __restrict__ bias, float* __restrict__ C,
            int M, int N, int K)
{
    __shared__ float As[16][64];
    __shared__ float Bs[16][64];

    const int tid = threadIdx.x;
    const int m0 = blockIdx.y * 64;
    const int n0 = blockIdx.x * 64;

    const int lr = tid >> 2;       // load row within tile (0..63)
    const int lc = tid & 3;        // float4 chunk within the 16-wide k slab
    const int tr = tid >> 4;       // compute: thread row group (0..15)
    const int tc = tid & 15;       // compute: thread col group (0..15)

    const float* Aptr = A + (size_t)(m0 + lr) * K + lc * 4;
    const float* Wptr = W + (size_t)(n0 + lr) * K + lc * 4;

    float acc[4][4];
#pragma unroll
    for (int i = 0; i < 4; i++)
#pragma unroll
        for (int j = 0; j < 4; j++) acc[i][j] = 0.0f;

    for (int k0 = 0; k0 < K; k0 += 16) {
        float4 av = *(const float4*)(Aptr + k0);
        float4 wv = *(const float4*)(Wptr + k0);
        As[lc * 4 + 0][lr] = av.x;
        As[lc * 4 + 1][lr] = av.y;
        As[lc * 4 + 2][lr] = av.z;
        As[lc * 4 + 3][lr] = av.w;
        Bs[lc * 4 + 0][lr] = wv.x;
        Bs[lc * 4 + 1][lr] = wv.y;
        Bs[lc * 4 + 2][lr] = wv.z;
        Bs[lc * 4 + 3][lr] = wv.w;
        __syncthreads();

#pragma unroll
        for (int kk = 0; kk < 16; kk++) {
            float4 a = *(const float4*)&As[kk][tr * 4];
            float4 b = *(const float4*)&Bs[kk][tc * 4];
            acc[0][0] += a.x * b.x; acc[0][1] += a.x * b.y;
            acc[0][2] += a.x * b.z; acc[0][3] += a.x * b.w;
            acc[1][0] += a.y * b.x; acc[1][1] += a.y * b.y;
            acc[1][2] += a.y * b.z; acc[1][3] += a.y * b.w;
            acc[2][0] += a.z * b.x; acc[2][1] += a.z * b.y;
            acc[2][2] += a.z * b.z; acc[2][3] += a.z * b.w;
            acc[3][0] += a.w * b.x; acc[3][1] += a.w * b.y;
            acc[3][2] += a.w * b.z; acc[3][3] += a.w * b.w;
        }
        __syncthreads();
    }

#pragma unroll
    for (int j = 0; j < 4; j++) {
        const int n = n0 + tc * 4 + j;
        const float bv = bias[n];
#pragma unroll
        for (int i = 0; i < 4; i++) {
            const int m = m0 + tr * 4 + i;
            const float v = acc[i][j] + bv;
            if (MODE == 0) {
                C[(size_t)m * N + n] = v;
            } else {
                const int b = m >> 11;          // m / S  (S=2048)
                const int s = m & 2047;         // m % S
                const int h = n >> 6;           // n / DK (DK=64)
                const int k = n & 63;           // n % DK
                C[((((size_t)b * HH + h) * SS + s) * DK) + k] = v;
            }
        }
    }
}

// ---------------------------------------------------------------------------
// Causal flash attention, fp32.
// Grid: (S/128, B*H).  128 threads; thread t owns query row qb*128 + t.
// K/V tiles of 64 rows x 64 cols staged in smem; online softmax in registers.
// Output written directly in concat-heads layout into g_Z.
// ---------------------------------------------------------------------------
__global__ __launch_bounds__(128)
void attn_kernel()
{
    __shared__ float Kt[64][64];
    __shared__ float Vt[64][64];

    const int qb = blockIdx.x;     // query block (0..15)
    const int bh = blockIdx.y;     // b*H + h     (0..63)
    const int t  = threadIdx.x;    // 0..127
    const int qi = qb * 128 + t;   // global query row in sequence

    const float* Qp = g_Q + ((size_t)bh * SS + qi) * DK;
    float q[DK];
#pragma unroll
    for (int d = 0; d < DK; d++) q[d] = Qp[d] * 0.125f;   // 1/sqrt(64)

    float o[DK];
#pragma unroll
    for (int d = 0; d < DK; d++) o[d] = 0.0f;
    float m = -1e30f;
    float l = 0.0f;

    const float* Kbase = g_K + (size_t)bh * SS * DK;
    const float* Vbase = g_V + (size_t)bh * SS * DK;

    const int nkt = 2 * qb + 2;    // key tiles needed (causal)
    for (int kt = 0; kt < nkt; kt++) {
        // cooperative tile load: 4096 floats each, 8 float4 per thread
        const float4* ksrc = (const float4*)(Kbase + (size_t)kt * 64 * DK);
        const float4* vsrc = (const float4*)(Vbase + (size_t)kt * 64 * DK);
        float4* kdst = (float4*)&Kt[0][0];
        float4* vdst = (float4*)&Vt[0][0];
#pragma unroll
        for (int i = 0; i < 8; i++) {
            kdst[t + i * 128] = ksrc[t + i * 128];
            vdst[t + i * 128] = vsrc[t + i * 128];
        }
        __syncthreads();

        const int jmax = min(64, qi - kt * 64 + 1);   // causal bound
        for (int j = 0; j < jmax; j++) {
            const float4* kr = (const float4*)Kt[j];
            float s0 = 0.f, s1 = 0.f, s2 = 0.f, s3 = 0.f;
#pragma unroll
            for (int d4 = 0; d4 < 16; d4++) {
                float4 kv = kr[d4];
                s0 += q[d4 * 4 + 0] * kv.x;
                s1 += q[d4 * 4 + 1] * kv.y;
                s2 += q[d4 * 4 + 2] * kv.z;
                s3 += q[d4 * 4 + 3] * kv.w;
            }
            const float s = (s0 + s1) + (s2 + s3);

            if (s > m) {
                const float corr = __expf(m - s);
                l *= corr;
#pragma unroll
                for (int d = 0; d < DK; d++) o[d] *= corr;
                m = s;
            }
            const float p = __expf(s - m);
            l += p;

            const float4* vr = (const float4*)Vt[j];
#pragma unroll
            for (int d4 = 0; d4 < 16; d4++) {
                float4 vv = vr[d4];
                o[d4 * 4 + 0] += p * vv.x;
                o[d4 * 4 + 1] += p * vv.y;
                o[d4 * 4 + 2] += p * vv.z;
                o[d4 * 4 + 3] += p * vv.w;
            }
        }
        __syncthreads();
    }

    const float inv = 1.0f / l;
    const int b = bh >> 4;     // bh / H
    const int h = bh & 15;     // bh % H
    float* outp = g_Z + ((size_t)b * SS + qi) * DD + h * DK;
#pragma unroll
    for (int d = 0; d < DK; d++) outp[d] = o[d] * inv;
}

// ---------------------------------------------------------------------------
// Launch: 3 projection GEMMs -> attention -> output projection
// Inputs (metadata order): query,key,value, Wq,bq, Wk,bk, Wv,bv, Wp,bp, mask
// mask is statically causal (tril) in the reference -> applied analytically.
// ---------------------------------------------------------------------------
extern "C" void kernel_launch(void* const* d_in, const int* in_sizes, int n_in,
                              void* d_out, int out_size)
{
    const float* query = (const float*)d_in[0];
    const float* key   = (const float*)d_in[1];
    const float* value = (const float*)d_in[2];
    const float* Wq    = (const float*)d_in[3];
    const float* bq    = (const float*)d_in[4];
    const float* Wk    = (const float*)d_in[5];
    const float* bk    = (const float*)d_in[6];
    const float* Wv    = (const float*)d_in[7];
    const float* bv    = (const float*)d_in[8];
    const float* Wp    = (const float*)d_in[9];
    const float* bp    = (const float*)d_in[10];
    // d_in[11] = mask (ignored: statically causal)

    float *Qd, *Kd, *Vd, *Zd;
    cudaGetSymbolAddress((void**)&Qd, g_Q);
    cudaGetSymbolAddress((void**)&Kd, g_K);
    cudaGetSymbolAddress((void**)&Vd, g_V);
    cudaGetSymbolAddress((void**)&Zd, g_Z);

    dim3 gg(DD / 64, MTOT / 64);   // (16, 128)

    gemm64<1><<<gg, 256>>>(query, Wq, bq, Qd, MTOT, DD, DD);
    gemm64<1><<<gg, 256>>>(key,   Wk, bk, Kd, MTOT, DD, DD);
    gemm64<1><<<gg, 256>>>(value, Wv, bv, Vd, MTOT, DD, DD);

    attn_kernel<<<dim3(SS / 128, BB * HH), 128>>>();

    gemm64<0><<<gg, 256>>>(Zd, Wp, bp, (float*)d_out, MTOT, DD, DD);
}

// round 4
// speedup vs baseline: 1.4753x; 1.4753x over previous
#include <cuda_runtime.h>
#include <cuda_bf16.h>
#include <cstdint>

// Problem constants
#define BB 4
#define SS 2048
#define HH 16
#define DD 1024
#define DK 64
#define MTOT (BB * SS)          // 8192

// ---------------------------------------------------------------------------
// Scratch (device globals — no runtime allocation allowed)
// ---------------------------------------------------------------------------
__device__ float g_Q[BB * HH * SS * DK];   // [b,h,s,k] fp32
__device__ float g_K[BB * HH * SS * DK];
__device__ float g_V[BB * HH * SS * DK];

__device__ __nv_bfloat16 g_qh[MTOT * DD], g_ql[MTOT * DD];
__device__ __nv_bfloat16 g_kh[MTOT * DD], g_kl[MTOT * DD];
__device__ __nv_bfloat16 g_vh[MTOT * DD], g_vl[MTOT * DD];
__device__ __nv_bfloat16 g_Zh[MTOT * DD], g_Zl[MTOT * DD];

__device__ __nv_bfloat16 g_Wqh[DD * DD], g_Wql[DD * DD];
__device__ __nv_bfloat16 g_Wkh[DD * DD], g_Wkl[DD * DD];
__device__ __nv_bfloat16 g_Wvh[DD * DD], g_Wvl[DD * DD];
__device__ __nv_bfloat16 g_Wph[DD * DD], g_Wpl[DD * DD];

// ---------------------------------------------------------------------------
// Portable PTX helpers (sm_80+ only: ldmatrix / mma.sync / cp.async)
// ---------------------------------------------------------------------------
__device__ __forceinline__ uint32_t smem_u32(const void* p) {
    uint32_t a;
    asm("{ .reg .u64 t; cvta.to.shared.u64 t, %1; cvt.u32.u64 %0, t; }"
        : "=r"(a) : "l"(p));
    return a;
}

__device__ __forceinline__ void ldsm4(uint32_t addr, uint32_t* r) {
    asm volatile("ldmatrix.sync.aligned.m8n8.x4.shared.b16 {%0,%1,%2,%3}, [%4];"
        : "=r"(r[0]), "=r"(r[1]), "=r"(r[2]), "=r"(r[3]) : "r"(addr));
}

__device__ __forceinline__ void mma16816(float* c, const uint32_t* a, const uint32_t* b) {
    asm volatile(
        "mma.sync.aligned.m16n8k16.row.col.f32.bf16.bf16.f32 "
        "{%0,%1,%2,%3}, {%4,%5,%6,%7}, {%8,%9}, {%0,%1,%2,%3};"
        : "+f"(c[0]), "+f"(c[1]), "+f"(c[2]), "+f"(c[3])
        : "r"(a[0]), "r"(a[1]), "r"(a[2]), "r"(a[3]), "r"(b[0]), "r"(b[1]));
}

__device__ __forceinline__ void cp16(uint32_t dst, const void* src) {
    asm volatile("cp.async.cg.shared.global [%0], [%1], 16;" :: "r"(dst), "l"(src));
}
#define CP_COMMIT asm volatile("cp.async.commit_group;" ::: "memory")
#define CP_WAIT1  asm volatile("cp.async.wait_group 1;" ::: "memory")
#define CP_WAIT0  asm volatile("cp.async.wait_group 0;" ::: "memory")

// ---------------------------------------------------------------------------
// fp32 -> (bf16 hi, bf16 lo) split conversion.  n must be a multiple of 1024.
// ---------------------------------------------------------------------------
__global__ __launch_bounds__(256)
void cvt_hilo(const float* __restrict__ x, __nv_bfloat16* __restrict__ hi,
              __nv_bfloat16* __restrict__ lo)
{
    const int i = (blockIdx.x * 256 + threadIdx.x) * 4;
    float4 v = *(const float4*)(x + i);
    float vv[4] = {v.x, v.y, v.z, v.w};
#pragma unroll
    for (int j = 0; j < 4; j++) {
        __nv_bfloat16 h = __float2bfloat16(vv[j]);
        hi[i + j] = h;
        lo[i + j] = __float2bfloat16(vv[j] - __bfloat162float(h));
    }
}

// ---------------------------------------------------------------------------
// mma.sync bf16-split GEMM: C[M,N] = (Ah+Al)[M,K] x (Wh+Wl)[N,K]^T + bias
// CTA 128x128, BK=32, double-buffered cp.async.  8 warps: 2(m) x 4(n),
// warp tile 64x32 = 4x4 m16n8k16 microtiles.  3 split products per k-chunk.
// MODE 0: C row-major [m, 1024]   MODE 1: scatter to [b,h,s,k]
// ---------------------------------------------------------------------------
#define AST 40                   // smem row stride in bf16 (80 B, conflict-free)
#define TILE_B (128 * AST * 2)   // 10240 bytes per 128x32 tile
#define STAGE_B (4 * TILE_B)     // Ah, Al, Wh, Wl
#define SMEM_GEMM (2 * STAGE_B)  // 81920 bytes

template <int MODE>
__global__ __launch_bounds__(256, 1)
void gemm_mma(const __nv_bfloat16* __restrict__ Ah, const __nv_bfloat16* __restrict__ Al,
              const __nv_bfloat16* __restrict__ Wh, const __nv_bfloat16* __restrict__ Wl,
              const float* __restrict__ bias, float* __restrict__ C)
{
    extern __shared__ __align__(16) char smem[];
    const uint32_t sb = smem_u32(smem);

    const int tid  = threadIdx.x;
    const int lane = tid & 31;
    const int wid  = tid >> 5;
    const int wm   = wid & 1;     // 0..1  (64-row group)
    const int wn   = wid >> 1;    // 0..3  (32-col group)
    const int m0 = blockIdx.y * 128;
    const int n0 = blockIdx.x * 128;

    const __nv_bfloat16* src[4] = {
        Ah + (size_t)m0 * DD, Al + (size_t)m0 * DD,
        Wh + (size_t)n0 * DD, Wl + (size_t)n0 * DD };

    // ---- async tile loader: 4 tiles x 128 rows x 32 bf16 (64B -> 4x16B) ----
    auto load_stage = [&](int stage, int ks) {
#pragma unroll
        for (int i = 0; i < 8; i++) {
            const int c   = tid + i * 256;       // 0..2047
            const int t   = c >> 9;              // tile 0..3
            const int cc  = c & 511;
            const int row = cc >> 2;             // 0..127
            const int ch  = cc & 3;              // 16B chunk
            cp16(sb + stage * STAGE_B + t * TILE_B + row * 80 + ch * 16,
                 src[t] + (size_t)row * DD + ks * 32 + ch * 8);
        }
    };

    float acc[4][4][4];
#pragma unroll
    for (int mi = 0; mi < 4; mi++)
#pragma unroll
        for (int ni = 0; ni < 4; ni++)
#pragma unroll
            for (int j = 0; j < 4; j++) acc[mi][ni][j] = 0.0f;

    load_stage(0, 0);
    CP_COMMIT;

    for (int ks = 0; ks < 32; ks++) {
        if (ks < 31) {
            load_stage((ks + 1) & 1, ks + 1);
            CP_COMMIT;
            CP_WAIT1;
        } else {
            CP_WAIT0;
        }
        __syncthreads();

        const uint32_t stb = sb + (ks & 1) * STAGE_B;
        const uint32_t sAh = stb;
        const uint32_t sAl = stb + TILE_B;
        const uint32_t sWh = stb + 2 * TILE_B;
        const uint32_t sWl = stb + 3 * TILE_B;

#pragma unroll
        for (int kk = 0; kk < 32; kk += 16) {
            // B fragments: 4 n-tiles (x4 ldmatrix covers 2 n-tiles each)
            uint32_t bh[4][2], bl[4][2];
#pragma unroll
            for (int np = 0; np < 2; np++) {
                const int g    = lane >> 3;
                const int brow = wn * 32 + np * 16 + ((g >> 1) << 3) + (lane & 7);
                const int bk   = kk + ((g & 1) << 3);
                uint32_t r[4];
                ldsm4(sWh + brow * 80 + bk * 2, r);
                bh[2 * np][0] = r[0]; bh[2 * np][1] = r[1];
                bh[2 * np + 1][0] = r[2]; bh[2 * np + 1][1] = r[3];
                ldsm4(sWl + brow * 80 + bk * 2, r);
                bl[2 * np][0] = r[0]; bl[2 * np][1] = r[1];
                bl[2 * np + 1][0] = r[2]; bl[2 * np + 1][1] = r[3];
            }
            // A fragments per m-tile, 3 split products
            const int arow_off = (lane & 15);
            const int ak = kk + ((lane >> 4) << 3);
#pragma unroll
            for (int mi = 0; mi < 4; mi++) {
                const int arow = wm * 64 + mi * 16 + arow_off;
                uint32_t ah[4], al[4];
                ldsm4(sAh + arow * 80 + ak * 2, ah);
                ldsm4(sAl + arow * 80 + ak * 2, al);
#pragma unroll
                for (int ni = 0; ni < 4; ni++) {
                    mma16816(acc[mi][ni], ah, bh[ni]);
                    mma16816(acc[mi][ni], al, bh[ni]);
                    mma16816(acc[mi][ni], ah, bl[ni]);
                }
            }
        }
        __syncthreads();
    }

    // ---- epilogue: acc layout c0,c1 @ (row l/4, col 2(l%4)+{0,1}), c2,c3 @ row+8
#pragma unroll
    for (int mi = 0; mi < 4; mi++) {
#pragma unroll
        for (int ni = 0; ni < 4; ni++) {
            const int row0 = m0 + wm * 64 + mi * 16 + (lane >> 2);
            const int col  = n0 + wn * 32 + ni * 8 + 2 * (lane & 3);
            const float b0 = __ldg(bias + col);
            const float b1 = __ldg(bias + col + 1);
            float2 v0 = make_float2(acc[mi][ni][0] + b0, acc[mi][ni][1] + b1);
            float2 v1 = make_float2(acc[mi][ni][2] + b0, acc[mi][ni][3] + b1);
            if (MODE == 0) {
                *(float2*)(C + (size_t)row0 * DD + col) = v0;
                *(float2*)(C + (size_t)(row0 + 8) * DD + col) = v1;
            } else {
                const int h = col >> 6, k = col & 63;
                {
                    const int b = row0 >> 11, s = row0 & 2047;
                    *(float2*)(C + (((size_t)b * HH + h) * SS + s) * DK + k) = v0;
                }
                {
                    const int r1 = row0 + 8;
                    const int b = r1 >> 11, s = r1 & 2047;
                    *(float2*)(C + (((size_t)b * HH + h) * SS + s) * DK + k) = v1;
                }
            }
        }
    }
}

// ---------------------------------------------------------------------------
// Causal flash attention, fp32; emits Z as bf16 hi/lo.
// ---------------------------------------------------------------------------
__global__ __launch_bounds__(128)
void attn_kernel()
{
    __shared__ float Kt[64][64];
    __shared__ float Vt[64][64];

    const int qb = blockIdx.x;
    const int bh = blockIdx.y;
    const int t  = threadIdx.x;
    const int qi = qb * 128 + t;

    const float* Qp = g_Q + ((size_t)bh * SS + qi) * DK;
    float q[DK];
#pragma unroll
    for (int d = 0; d < DK; d++) q[d] = Qp[d] * 0.125f;   // 1/sqrt(64)

    float o[DK];
#pragma unroll
    for (int d = 0; d < DK; d++) o[d] = 0.0f;
    float m = -1e30f;
    float l = 0.0f;

    const float* Kbase = g_K + (size_t)bh * SS * DK;
    const float* Vbase = g_V + (size_t)bh * SS * DK;

    const int nkt = 2 * qb + 2;
    for (int kt = 0; kt < nkt; kt++) {
        const float4* ksrc = (const float4*)(Kbase + (size_t)kt * 64 * DK);
        const float4* vsrc = (const float4*)(Vbase + (size_t)kt * 64 * DK);
        float4* kdst = (float4*)&Kt[0][0];
        float4* vdst = (float4*)&Vt[0][0];
#pragma unroll
        for (int i = 0; i < 8; i++) {
            kdst[t + i * 128] = ksrc[t + i * 128];
            vdst[t + i * 128] = vsrc[t + i * 128];
        }
        __syncthreads();

        const int jmax = min(64, qi - kt * 64 + 1);
        for (int j = 0; j < jmax; j++) {
            const float4* kr = (const float4*)Kt[j];
            float s0 = 0.f, s1 = 0.f, s2 = 0.f, s3 = 0.f;
#pragma unroll
            for (int d4 = 0; d4 < 16; d4++) {
                float4 kv = kr[d4];
                s0 += q[d4 * 4 + 0] * kv.x;
                s1 += q[d4 * 4 + 1] * kv.y;
                s2 += q[d4 * 4 + 2] * kv.z;
                s3 += q[d4 * 4 + 3] * kv.w;
            }
            const float s = (s0 + s1) + (s2 + s3);

            if (s > m) {
                const float corr = __expf(m - s);
                l *= corr;
#pragma unroll
                for (int d = 0; d < DK; d++) o[d] *= corr;
                m = s;
            }
            const float p = __expf(s - m);
            l += p;

            const float4* vr = (const float4*)Vt[j];
#pragma unroll
            for (int d4 = 0; d4 < 16; d4++) {
                float4 vv = vr[d4];
                o[d4 * 4 + 0] += p * vv.x;
                o[d4 * 4 + 1] += p * vv.y;
                o[d4 * 4 + 2] += p * vv.z;
                o[d4 * 4 + 3] += p * vv.w;
            }
        }
        __syncthreads();
    }

    const float inv = 1.0f / l;
    const int b  = bh >> 4;
    const int hh = bh & 15;
    const size_t off = ((size_t)b * SS + qi) * DD + hh * DK;
#pragma unroll
    for (int d = 0; d < DK; d++) {
        const float v = o[d] * inv;
        const __nv_bfloat16 vh = __float2bfloat16(v);
        g_Zh[off + d] = vh;
        g_Zl[off + d] = __float2bfloat16(v - __bfloat162float(vh));
    }
}

// ---------------------------------------------------------------------------
// Launch
// ---------------------------------------------------------------------------
extern "C" void kernel_launch(void* const* d_in, const int* in_sizes, int n_in,
                              void* d_out, int out_size)
{
    const float* query = (const float*)d_in[0];
    const float* key   = (const float*)d_in[1];
    const float* value = (const float*)d_in[2];
    const float* Wq    = (const float*)d_in[3];
    const float* bq    = (const float*)d_in[4];
    const float* Wk    = (const float*)d_in[5];
    const float* bk    = (const float*)d_in[6];
    const float* Wv    = (const float*)d_in[7];
    const float* bv    = (const float*)d_in[8];
    const float* Wp    = (const float*)d_in[9];
    const float* bp    = (const float*)d_in[10];
    // d_in[11] = mask (statically causal -> applied analytically)

    float *Qd, *Kd, *Vd;
    __nv_bfloat16 *qh, *ql, *kh, *kl, *vh, *vl, *Zh, *Zl;
    __nv_bfloat16 *Wqh, *Wql, *Wkh, *Wkl, *Wvh, *Wvl, *Wph, *Wpl;
    cudaGetSymbolAddress((void**)&Qd, g_Q);
    cudaGetSymbolAddress((void**)&Kd, g_K);
    cudaGetSymbolAddress((void**)&Vd, g_V);
    cudaGetSymbolAddress((void**)&qh, g_qh);  cudaGetSymbolAddress((void**)&ql, g_ql);
    cudaGetSymbolAddress((void**)&kh, g_kh);  cudaGetSymbolAddress((void**)&kl, g_kl);
    cudaGetSymbolAddress((void**)&vh, g_vh);  cudaGetSymbolAddress((void**)&vl, g_vl);
    cudaGetSymbolAddress((void**)&Zh, g_Zh);  cudaGetSymbolAddress((void**)&Zl, g_Zl);
    cudaGetSymbolAddress((void**)&Wqh, g_Wqh); cudaGetSymbolAddress((void**)&Wql, g_Wql);
    cudaGetSymbolAddress((void**)&Wkh, g_Wkh); cudaGetSymbolAddress((void**)&Wkl, g_Wkl);
    cudaGetSymbolAddress((void**)&Wvh, g_Wvh); cudaGetSymbolAddress((void**)&Wvl, g_Wvl);
    cudaGetSymbolAddress((void**)&Wph, g_Wph); cudaGetSymbolAddress((void**)&Wpl, g_Wpl);

    cudaFuncSetAttribute(gemm_mma<0>, cudaFuncAttributeMaxDynamicSharedMemorySize, SMEM_GEMM);
    cudaFuncSetAttribute(gemm_mma<1>, cudaFuncAttributeMaxDynamicSharedMemorySize, SMEM_GEMM);

    // fp32 -> bf16 hi/lo conversions
    cvt_hilo<<<MTOT * DD / 1024, 256>>>(query, qh, ql);
    cvt_hilo<<<MTOT * DD / 1024, 256>>>(key,   kh, kl);
    cvt_hilo<<<MTOT * DD / 1024, 256>>>(value, vh, vl);
    cvt_hilo<<<DD * DD / 1024, 256>>>(Wq, Wqh, Wql);
    cvt_hilo<<<DD * DD / 1024, 256>>>(Wk, Wkh, Wkl);
    cvt_hilo<<<DD * DD / 1024, 256>>>(Wv, Wvh, Wvl);
    cvt_hilo<<<DD * DD / 1024, 256>>>(Wp, Wph, Wpl);

    const dim3 gg(DD / 128, MTOT / 128);   // (8, 64)

    gemm_mma<1><<<gg, 256, SMEM_GEMM>>>(qh, ql, Wqh, Wql, bq, Qd);
    gemm_mma<1><<<gg, 256, SMEM_GEMM>>>(kh, kl, Wkh, Wkl, bk, Kd);
    gemm_mma<1><<<gg, 256, SMEM_GEMM>>>(vh, vl, Wvh, Wvl, bv, Vd);

    attn_kernel<<<dim3(SS / 128, BB * HH), 128>>>();

    gemm_mma<0><<<gg, 256, SMEM_GEMM>>>(Zh, Zl, Wph, Wpl, bp, (float*)d_out);
}

// round 5
// speedup vs baseline: 3.1632x; 2.1442x over previous
#include <cuda_runtime.h>
#include <cuda_bf16.h>
#include <cstdint>

// Problem constants
#define BB 4
#define SS 2048
#define HH 16
#define DD 1024
#define DK 64
#define MTOT (BB * SS)          // 8192

// ---------------------------------------------------------------------------
// Scratch (device globals — no runtime allocation allowed)
// ---------------------------------------------------------------------------
// bf16 hi/lo split of the raw inputs (GEMM A operands)
__device__ __nv_bfloat16 g_qh[MTOT * DD], g_ql[MTOT * DD];
__device__ __nv_bfloat16 g_kh[MTOT * DD], g_kl[MTOT * DD];
__device__ __nv_bfloat16 g_vh[MTOT * DD], g_vl[MTOT * DD];
// projected Q/K/V in [b,h,s,k], bf16 hi/lo
__device__ __nv_bfloat16 g_QPh[MTOT * DD], g_QPl[MTOT * DD];
__device__ __nv_bfloat16 g_KPh[MTOT * DD], g_KPl[MTOT * DD];
__device__ __nv_bfloat16 g_VPh[MTOT * DD], g_VPl[MTOT * DD];
// attention output (concat heads), bf16 hi/lo
__device__ __nv_bfloat16 g_Zh[MTOT * DD], g_Zl[MTOT * DD];
// weights, bf16 hi/lo
__device__ __nv_bfloat16 g_Wqh[DD * DD], g_Wql[DD * DD];
__device__ __nv_bfloat16 g_Wkh[DD * DD], g_Wkl[DD * DD];
__device__ __nv_bfloat16 g_Wvh[DD * DD], g_Wvl[DD * DD];
__device__ __nv_bfloat16 g_Wph[DD * DD], g_Wpl[DD * DD];

// ---------------------------------------------------------------------------
// Portable PTX helpers (sm_80+: ldmatrix / mma.sync / cp.async)
// ---------------------------------------------------------------------------
__device__ __forceinline__ uint32_t smem_u32(const void* p) {
    uint32_t a;
    asm("{ .reg .u64 t; cvta.to.shared.u64 t, %1; cvt.u32.u64 %0, t; }"
        : "=r"(a) : "l"(p));
    return a;
}

__device__ __forceinline__ void ldsm4(uint32_t addr, uint32_t* r) {
    asm volatile("ldmatrix.sync.aligned.m8n8.x4.shared.b16 {%0,%1,%2,%3}, [%4];"
        : "=r"(r[0]), "=r"(r[1]), "=r"(r[2]), "=r"(r[3]) : "r"(addr));
}

__device__ __forceinline__ void ldsm4t(uint32_t addr, uint32_t* r) {
    asm volatile("ldmatrix.sync.aligned.m8n8.x4.trans.shared.b16 {%0,%1,%2,%3}, [%4];"
        : "=r"(r[0]), "=r"(r[1]), "=r"(r[2]), "=r"(r[3]) : "r"(addr));
}

__device__ __forceinline__ void mma16816(float* c, const uint32_t* a, const uint32_t* b) {
    asm volatile(
        "mma.sync.aligned.m16n8k16.row.col.f32.bf16.bf16.f32 "
        "{%0,%1,%2,%3}, {%4,%5,%6,%7}, {%8,%9}, {%0,%1,%2,%3};"
        : "+f"(c[0]), "+f"(c[1]), "+f"(c[2]), "+f"(c[3])
        : "r"(a[0]), "r"(a[1]), "r"(a[2]), "r"(a[3]), "r"(b[0]), "r"(b[1]));
}

__device__ __forceinline__ void cp16(uint32_t dst, const void* src) {
    asm volatile("cp.async.cg.shared.global [%0], [%1], 16;" :: "r"(dst), "l"(src));
}
#define CP_COMMIT asm volatile("cp.async.commit_group;" ::: "memory")
#define CP_WAIT1  asm volatile("cp.async.wait_group 1;" ::: "memory")
#define CP_WAIT0  asm volatile("cp.async.wait_group 0;" ::: "memory")

// pack (a,b) -> bf16x2 hi word + bf16x2 residual word (lo half = first arg)
__device__ __forceinline__ void hilo2(float a, float b, uint32_t& h, uint32_t& l) {
    __nv_bfloat162 hh = __floats2bfloat162_rn(a, b);
    float ra = a - __bfloat162float(hh.x);
    float rb = b - __bfloat162float(hh.y);
    __nv_bfloat162 ll = __floats2bfloat162_rn(ra, rb);
    h = *(uint32_t*)&hh;
    l = *(uint32_t*)&ll;
}

// ---------------------------------------------------------------------------
// fp32 -> (bf16 hi, bf16 lo) split conversion.
// ---------------------------------------------------------------------------
__global__ __launch_bounds__(256)
void cvt_hilo(const float* __restrict__ x, __nv_bfloat16* __restrict__ hi,
              __nv_bfloat16* __restrict__ lo)
{
    const int i = (blockIdx.x * 256 + threadIdx.x) * 4;
    float4 v = *(const float4*)(x + i);
    float vv[4] = {v.x, v.y, v.z, v.w};
#pragma unroll
    for (int j = 0; j < 4; j++) {
        __nv_bfloat16 h = __float2bfloat16(vv[j]);
        hi[i + j] = h;
        lo[i + j] = __float2bfloat16(vv[j] - __bfloat162float(h));
    }
}

// ---------------------------------------------------------------------------
// mma.sync bf16-split GEMM: C = (Ah+Al)[M,K] x (Wh+Wl)[N,K]^T + bias
// CTA 128x128, BK=32, double-buffered cp.async, 8 warps (2m x 4n), 64x32/warp.
// MODE 0: fp32 row-major to Cf.  MODE 1: bf16 hi/lo scatter to [b,h,s,k].
// ---------------------------------------------------------------------------
#define TILE_B (128 * 80)        // 10240 bytes per 128x32 tile (80B rows)
#define STAGE_B (4 * TILE_B)
#define SMEM_GEMM (2 * STAGE_B)  // 81920

template <int MODE>
__global__ __launch_bounds__(256, 1)
void gemm_mma(const __nv_bfloat16* __restrict__ Ah, const __nv_bfloat16* __restrict__ Al,
              const __nv_bfloat16* __restrict__ Wh, const __nv_bfloat16* __restrict__ Wl,
              const float* __restrict__ bias, float* __restrict__ Cf,
              __nv_bfloat16* __restrict__ Chi, __nv_bfloat16* __restrict__ Clo)
{
    extern __shared__ __align__(16) char smem[];
    const uint32_t sb = smem_u32(smem);

    const int tid  = threadIdx.x;
    const int lane = tid & 31;
    const int wid  = tid >> 5;
    const int wm   = wid & 1;
    const int wn   = wid >> 1;
    const int m0 = blockIdx.y * 128;
    const int n0 = blockIdx.x * 128;

    const __nv_bfloat16* src[4] = {
        Ah + (size_t)m0 * DD, Al + (size_t)m0 * DD,
        Wh + (size_t)n0 * DD, Wl + (size_t)n0 * DD };

    auto load_stage = [&](int stage, int ks) {
#pragma unroll
        for (int i = 0; i < 8; i++) {
            const int c   = tid + i * 256;
            const int t   = c >> 9;
            const int cc  = c & 511;
            const int row = cc >> 2;
            const int ch  = cc & 3;
            cp16(sb + stage * STAGE_B + t * TILE_B + row * 80 + ch * 16,
                 src[t] + (size_t)row * DD + ks * 32 + ch * 8);
        }
    };

    float acc[4][4][4];
#pragma unroll
    for (int mi = 0; mi < 4; mi++)
#pragma unroll
        for (int ni = 0; ni < 4; ni++)
#pragma unroll
            for (int j = 0; j < 4; j++) acc[mi][ni][j] = 0.0f;

    load_stage(0, 0);
    CP_COMMIT;

    for (int ks = 0; ks < 32; ks++) {
        if (ks < 31) {
            load_stage((ks + 1) & 1, ks + 1);
            CP_COMMIT;
            CP_WAIT1;
        } else {
            CP_WAIT0;
        }
        __syncthreads();

        const uint32_t stb = sb + (ks & 1) * STAGE_B;
        const uint32_t sAh = stb;
        const uint32_t sAl = stb + TILE_B;
        const uint32_t sWh = stb + 2 * TILE_B;
        const uint32_t sWl = stb + 3 * TILE_B;

#pragma unroll
        for (int kk = 0; kk < 32; kk += 16) {
            uint32_t bh[4][2], bl[4][2];
#pragma unroll
            for (int np = 0; np < 2; np++) {
                const int g    = lane >> 3;
                const int brow = wn * 32 + np * 16 + ((g >> 1) << 3) + (lane & 7);
                const int bk   = kk + ((g & 1) << 3);
                uint32_t r[4];
                ldsm4(sWh + brow * 80 + bk * 2, r);
                bh[2 * np][0] = r[0]; bh[2 * np][1] = r[1];
                bh[2 * np + 1][0] = r[2]; bh[2 * np + 1][1] = r[3];
                ldsm4(sWl + brow * 80 + bk * 2, r);
                bl[2 * np][0] = r[0]; bl[2 * np][1] = r[1];
                bl[2 * np + 1][0] = r[2]; bl[2 * np + 1][1] = r[3];
            }
            const int arow_off = (lane & 15);
            const int ak = kk + ((lane >> 4) << 3);
#pragma unroll
            for (int mi = 0; mi < 4; mi++) {
                const int arow = wm * 64 + mi * 16 + arow_off;
                uint32_t ah[4], al[4];
                ldsm4(sAh + arow * 80 + ak * 2, ah);
                ldsm4(sAl + arow * 80 + ak * 2, al);
#pragma unroll
                for (int ni = 0; ni < 4; ni++) {
                    mma16816(acc[mi][ni], ah, bh[ni]);
                    mma16816(acc[mi][ni], al, bh[ni]);
                    mma16816(acc[mi][ni], ah, bl[ni]);
                }
            }
        }
        __syncthreads();
    }

#pragma unroll
    for (int mi = 0; mi < 4; mi++) {
#pragma unroll
        for (int ni = 0; ni < 4; ni++) {
            const int row0 = m0 + wm * 64 + mi * 16 + (lane >> 2);
            const int col  = n0 + wn * 32 + ni * 8 + 2 * (lane & 3);
            const float b0 = __ldg(bias + col);
            const float b1 = __ldg(bias + col + 1);
            const float v00 = acc[mi][ni][0] + b0, v01 = acc[mi][ni][1] + b1;
            const float v10 = acc[mi][ni][2] + b0, v11 = acc[mi][ni][3] + b1;
            if (MODE == 0) {
                *(float2*)(Cf + (size_t)row0 * DD + col) = make_float2(v00, v01);
                *(float2*)(Cf + (size_t)(row0 + 8) * DD + col) = make_float2(v10, v11);
            } else {
                const int h = col >> 6, k = col & 63;
                uint32_t ph, pl;
                {
                    const int b = row0 >> 11, s = row0 & 2047;
                    const size_t o = (((size_t)b * HH + h) * SS + s) * DK + k;
                    hilo2(v00, v01, ph, pl);
                    *(uint32_t*)(Chi + o) = ph;
                    *(uint32_t*)(Clo + o) = pl;
                }
                {
                    const int r1 = row0 + 8;
                    const int b = r1 >> 11, s = r1 & 2047;
                    const size_t o = (((size_t)b * HH + h) * SS + s) * DK + k;
                    hilo2(v10, v11, ph, pl);
                    *(uint32_t*)(Chi + o) = ph;
                    *(uint32_t*)(Clo + o) = pl;
                }
            }
        }
    }
}

// ---------------------------------------------------------------------------
// Causal flash attention on mma.sync bf16 with hi/lo split.
// CTA = 64 q rows (4 warps x 16), K/V blocks of 64, double-buffered cp.async.
// Grid: (S/64, B*H).
// ---------------------------------------------------------------------------
#define ROWB 144                   // 64 bf16 data + 16B pad (odd 16B multiple)
#define KVTILE (64 * ROWB)         // 9216
#define STG (4 * KVTILE)           // Kh, Kl, Vh, Vl = 36864
#define SMEM_ATT (2 * STG)         // 73728

__global__ __launch_bounds__(128)
void attn_mma()
{
    extern __shared__ __align__(16) char smem[];
    const uint32_t sb = smem_u32(smem);
    const int tid  = threadIdx.x;
    const int lane = tid & 31;
    const int w    = tid >> 5;
    const int qb   = blockIdx.x;    // 0..31
    const int bh   = blockIdx.y;    // 0..63

    const size_t hoff = (size_t)bh * SS * DK;
    const __nv_bfloat16* kvsrc[4] = {
        g_KPh + hoff, g_KPl + hoff, g_VPh + hoff, g_VPl + hoff };

    auto load_kv = [&](int kb, int stage) {
        const size_t base = (size_t)kb * 64 * DK;
#pragma unroll
        for (int i = 0; i < 16; i++) {
            const int c   = tid + i * 128;   // 0..2047
            const int t   = c >> 9;
            const int cc  = c & 511;
            const int row = cc >> 3;
            const int ch  = cc & 7;
            cp16(sb + stage * STG + t * KVTILE + row * ROWB + ch * 16,
                 kvsrc[t] + base + row * DK + ch * 8);
        }
    };

    // ---- prologue: Q tile (hi/lo) into buf1 region, KV block 0 into buf0 ----
    {
        const __nv_bfloat16* qsrc[2] = {
            g_QPh + hoff + (size_t)qb * 64 * DK,
            g_QPl + hoff + (size_t)qb * 64 * DK };
#pragma unroll
        for (int i = 0; i < 8; i++) {
            const int c   = tid + i * 128;   // 0..1023
            const int t   = c >> 9;
            const int cc  = c & 511;
            const int row = cc >> 3;
            const int ch  = cc & 7;
            cp16(sb + STG + t * KVTILE + row * ROWB + ch * 16,
                 qsrc[t] + row * DK + ch * 8);
        }
    }
    CP_COMMIT;
    load_kv(0, 0);
    CP_COMMIT;
    CP_WAIT1;                      // Q done (KV0 may still be in flight)
    __syncthreads();

    uint32_t qfh[4][4], qfl[4][4];
#pragma unroll
    for (int kc = 0; kc < 4; kc++) {
        const int row = w * 16 + (lane & 15);
        const int k   = kc * 16 + ((lane >> 4) << 3);
        ldsm4(sb + STG + row * ROWB + k * 2, qfh[kc]);
        ldsm4(sb + STG + KVTILE + row * ROWB + k * 2, qfl[kc]);
    }
    __syncthreads();               // Q frags read before buf1 gets overwritten

    float co[8][4];
#pragma unroll
    for (int n = 0; n < 8; n++)
#pragma unroll
        for (int j = 0; j < 4; j++) co[n][j] = 0.0f;
    float m0v = -1e30f, m1v = -1e30f, l0 = 0.0f, l1 = 0.0f;

    for (int kb = 0; kb <= qb; kb++) {
        if (kb < qb) {
            load_kv(kb + 1, (kb + 1) & 1);
            CP_COMMIT;
            CP_WAIT1;
        } else {
            CP_WAIT0;
        }
        __syncthreads();

        const uint32_t stb = sb + (kb & 1) * STG;

        // ---- S = Q K^T (3 split products), fp32 acc ----
        float c[8][4];
#pragma unroll
        for (int n = 0; n < 8; n++)
#pragma unroll
            for (int j = 0; j < 4; j++) c[n][j] = 0.0f;

#pragma unroll
        for (int kc = 0; kc < 4; kc++) {
            uint32_t kfh[8][2], kfl[8][2];
#pragma unroll
            for (int p = 0; p < 4; p++) {
                const int g    = lane >> 3;
                const int brow = p * 16 + ((g >> 1) << 3) + (lane & 7);
                const int bk   = kc * 16 + ((g & 1) << 3);
                uint32_t r[4];
                ldsm4(stb + brow * ROWB + bk * 2, r);
                kfh[2 * p][0] = r[0]; kfh[2 * p][1] = r[1];
                kfh[2 * p + 1][0] = r[2]; kfh[2 * p + 1][1] = r[3];
                ldsm4(stb + KVTILE + brow * ROWB + bk * 2, r);
                kfl[2 * p][0] = r[0]; kfl[2 * p][1] = r[1];
                kfl[2 * p + 1][0] = r[2]; kfl[2 * p + 1][1] = r[3];
            }
#pragma unroll
            for (int n = 0; n < 8; n++) {
                mma16816(c[n], qfh[kc], kfh[n]);
                mma16816(c[n], qfl[kc], kfh[n]);
                mma16816(c[n], qfh[kc], kfl[n]);
            }
        }

        // ---- softmax (scale 1/8, causal mask on diagonal block) ----
        const bool diag = (kb == qb);
        const int r0 = lane >> 2, r1 = r0 + 8;
        const int rowloc = w * 16;
        float mx0 = -1e30f, mx1 = -1e30f;
#pragma unroll
        for (int n = 0; n < 8; n++) {
#pragma unroll
            for (int j = 0; j < 4; j++) {
                c[n][j] *= 0.125f;
                if (diag) {
                    const int col = n * 8 + 2 * (lane & 3) + (j & 1);
                    const int row = rowloc + ((j < 2) ? r0 : r1);
                    if (col > row) c[n][j] = -1e30f;
                }
            }
            mx0 = fmaxf(mx0, fmaxf(c[n][0], c[n][1]));
            mx1 = fmaxf(mx1, fmaxf(c[n][2], c[n][3]));
        }
        mx0 = fmaxf(mx0, __shfl_xor_sync(0xffffffff, mx0, 1));
        mx0 = fmaxf(mx0, __shfl_xor_sync(0xffffffff, mx0, 2));
        mx1 = fmaxf(mx1, __shfl_xor_sync(0xffffffff, mx1, 1));
        mx1 = fmaxf(mx1, __shfl_xor_sync(0xffffffff, mx1, 2));

        const float mn0 = fmaxf(m0v, mx0), mn1 = fmaxf(m1v, mx1);
        const float cor0 = __expf(m0v - mn0), cor1 = __expf(m1v - mn1);
        m0v = mn0; m1v = mn1;

        float s0 = 0.0f, s1 = 0.0f;
#pragma unroll
        for (int n = 0; n < 8; n++) {
            c[n][0] = __expf(c[n][0] - mn0);
            c[n][1] = __expf(c[n][1] - mn0);
            c[n][2] = __expf(c[n][2] - mn1);
            c[n][3] = __expf(c[n][3] - mn1);
            s0 += c[n][0] + c[n][1];
            s1 += c[n][2] + c[n][3];
        }
        s0 += __shfl_xor_sync(0xffffffff, s0, 1);
        s0 += __shfl_xor_sync(0xffffffff, s0, 2);
        s1 += __shfl_xor_sync(0xffffffff, s1, 1);
        s1 += __shfl_xor_sync(0xffffffff, s1, 2);
        l0 = l0 * cor0 + s0;
        l1 = l1 * cor1 + s1;
#pragma unroll
        for (int n = 0; n < 8; n++) {
            co[n][0] *= cor0; co[n][1] *= cor0;
            co[n][2] *= cor1; co[n][3] *= cor1;
        }

        // ---- pack P as bf16 hi/lo A-fragments ----
        uint32_t pah[4][4], pal[4][4];
#pragma unroll
        for (int kc = 0; kc < 4; kc++) {
            hilo2(c[2 * kc][0],     c[2 * kc][1],     pah[kc][0], pal[kc][0]);
            hilo2(c[2 * kc][2],     c[2 * kc][3],     pah[kc][1], pal[kc][1]);
            hilo2(c[2 * kc + 1][0], c[2 * kc + 1][1], pah[kc][2], pal[kc][2]);
            hilo2(c[2 * kc + 1][2], c[2 * kc + 1][3], pah[kc][3], pal[kc][3]);
        }

        // ---- O += P V (3 split products); V via ldmatrix.trans ----
#pragma unroll
        for (int kc = 0; kc < 4; kc++) {
            uint32_t vfh[8][2], vfl[8][2];
#pragma unroll
            for (int dp = 0; dp < 4; dp++) {
                const int g    = lane >> 3;
                const int j    = lane & 7;
                const int srow = kc * 16 + ((g & 1) << 3) + j;
                const int dcol = dp * 16 + ((g >> 1) << 3);
                uint32_t r[4];
                ldsm4t(stb + 2 * KVTILE + srow * ROWB + dcol * 2, r);
                vfh[2 * dp][0] = r[0]; vfh[2 * dp][1] = r[1];
                vfh[2 * dp + 1][0] = r[2]; vfh[2 * dp + 1][1] = r[3];
                ldsm4t(stb + 3 * KVTILE + srow * ROWB + dcol * 2, r);
                vfl[2 * dp][0] = r[0]; vfl[2 * dp][1] = r[1];
                vfl[2 * dp + 1][0] = r[2]; vfl[2 * dp + 1][1] = r[3];
            }
#pragma unroll
            for (int n = 0; n < 8; n++) {
                mma16816(co[n], pah[kc], vfh[n]);
                mma16816(co[n], pal[kc], vfh[n]);
                mma16816(co[n], pah[kc], vfl[n]);
            }
        }
        __syncthreads();   // all warps done with this buffer before reuse
    }

    // ---- epilogue: O /= l, write concat-heads bf16 hi/lo ----
    const float i0 = 1.0f / l0, i1 = 1.0f / l1;
    const int b  = bh >> 4;
    const int hh = bh & 15;
    const int q0 = qb * 64 + w * 16 + (lane >> 2);
#pragma unroll
    for (int n = 0; n < 8; n++) {
        const int dk = n * 8 + 2 * (lane & 3);
        const size_t o0 = ((size_t)b * SS + q0) * DD + hh * 64 + dk;
        const size_t o1 = o0 + (size_t)8 * DD;
        uint32_t ph, pl;
        hilo2(co[n][0] * i0, co[n][1] * i0, ph, pl);
        *(uint32_t*)(g_Zh + o0) = ph;
        *(uint32_t*)(g_Zl + o0) = pl;
        hilo2(co[n][2] * i1, co[n][3] * i1, ph, pl);
        *(uint32_t*)(g_Zh + o1) = ph;
        *(uint32_t*)(g_Zl + o1) = pl;
    }
}

// ---------------------------------------------------------------------------
// Launch
// ---------------------------------------------------------------------------
extern "C" void kernel_launch(void* const* d_in, const int* in_sizes, int n_in,
                              void* d_out, int out_size)
{
    const float* query = (const float*)d_in[0];
    const float* key   = (const float*)d_in[1];
    const float* value = (const float*)d_in[2];
    const float* Wq    = (const float*)d_in[3];
    const float* bq    = (const float*)d_in[4];
    const float* Wk    = (const float*)d_in[5];
    const float* bk    = (const float*)d_in[6];
    const float* Wv    = (const float*)d_in[7];
    const float* bv    = (const float*)d_in[8];
    const float* Wp    = (const float*)d_in[9];
    const float* bp    = (const float*)d_in[10];
    // d_in[11] = mask (statically causal -> applied analytically)

    __nv_bfloat16 *qh, *ql, *kh, *kl, *vh, *vl;
    __nv_bfloat16 *QPh, *QPl, *KPh, *KPl, *VPh, *VPl, *Zh, *Zl;
    __nv_bfloat16 *Wqh, *Wql, *Wkh, *Wkl, *Wvh, *Wvl, *Wph, *Wpl;
    cudaGetSymbolAddress((void**)&qh, g_qh);   cudaGetSymbolAddress((void**)&ql, g_ql);
    cudaGetSymbolAddress((void**)&kh, g_kh);   cudaGetSymbolAddress((void**)&kl, g_kl);
    cudaGetSymbolAddress((void**)&vh, g_vh);   cudaGetSymbolAddress((void**)&vl, g_vl);
    cudaGetSymbolAddress((void**)&QPh, g_QPh); cudaGetSymbolAddress((void**)&QPl, g_QPl);
    cudaGetSymbolAddress((void**)&KPh, g_KPh); cudaGetSymbolAddress((void**)&KPl, g_KPl);
    cudaGetSymbolAddress((void**)&VPh, g_VPh); cudaGetSymbolAddress((void**)&VPl, g_VPl);
    cudaGetSymbolAddress((void**)&Zh, g_Zh);   cudaGetSymbolAddress((void**)&Zl, g_Zl);
    cudaGetSymbolAddress((void**)&Wqh, g_Wqh); cudaGetSymbolAddress((void**)&Wql, g_Wql);
    cudaGetSymbolAddress((void**)&Wkh, g_Wkh); cudaGetSymbolAddress((void**)&Wkl, g_Wkl);
    cudaGetSymbolAddress((void**)&Wvh, g_Wvh); cudaGetSymbolAddress((void**)&Wvl, g_Wvl);
    cudaGetSymbolAddress((void**)&Wph, g_Wph); cudaGetSymbolAddress((void**)&Wpl, g_Wpl);

    cudaFuncSetAttribute(gemm_mma<0>, cudaFuncAttributeMaxDynamicSharedMemorySize, SMEM_GEMM);
    cudaFuncSetAttribute(gemm_mma<1>, cudaFuncAttributeMaxDynamicSharedMemorySize, SMEM_GEMM);
    cudaFuncSetAttribute(attn_mma, cudaFuncAttributeMaxDynamicSharedMemorySize, SMEM_ATT);

    // fp32 -> bf16 hi/lo conversions
    cvt_hilo<<<MTOT * DD / 1024, 256>>>(query, qh, ql);
    cvt_hilo<<<MTOT * DD / 1024, 256>>>(key,   kh, kl);
    cvt_hilo<<<MTOT * DD / 1024, 256>>>(value, vh, vl);
    cvt_hilo<<<DD * DD / 1024, 256>>>(Wq, Wqh, Wql);
    cvt_hilo<<<DD * DD / 1024, 256>>>(Wk, Wkh, Wkl);
    cvt_hilo<<<DD * DD / 1024, 256>>>(Wv, Wvh, Wvl);
    cvt_hilo<<<DD * DD / 1024, 256>>>(Wp, Wph, Wpl);

    const dim3 gg(DD / 128, MTOT / 128);   // (8, 64)

    gemm_mma<1><<<gg, 256, SMEM_GEMM>>>(qh, ql, Wqh, Wql, bq, nullptr, QPh, QPl);
    gemm_mma<1><<<gg, 256, SMEM_GEMM>>>(kh, kl, Wkh, Wkl, bk, nullptr, KPh, KPl);
    gemm_mma<1><<<gg, 256, SMEM_GEMM>>>(vh, vl, Wvh, Wvl, bv, nullptr, VPh, VPl);

    attn_mma<<<dim3(SS / 64, BB * HH), 128, SMEM_ATT>>>();

    gemm_mma<0><<<gg, 256, SMEM_GEMM>>>(Zh, Zl, Wph, Wpl, bp, (float*)d_out, nullptr, nullptr);
}

// round 6
// speedup vs baseline: 3.4939x; 1.1045x over previous
#include <cuda_runtime.h>
#include <cuda_bf16.h>
#include <cstdint>

// Problem constants
#define BB 4
#define SS 2048
#define HH 16
#define DD 1024
#define DK 64
#define MTOT (BB * SS)          // 8192

// ---------------------------------------------------------------------------
// Scratch (device globals — no runtime allocation allowed)
// ---------------------------------------------------------------------------
__device__ __nv_bfloat16 g_qh[MTOT * DD], g_ql[MTOT * DD];
__device__ __nv_bfloat16 g_kh[MTOT * DD], g_kl[MTOT * DD];
__device__ __nv_bfloat16 g_vh[MTOT * DD], g_vl[MTOT * DD];
__device__ __nv_bfloat16 g_QPh[MTOT * DD], g_QPl[MTOT * DD];
__device__ __nv_bfloat16 g_KPh[MTOT * DD], g_KPl[MTOT * DD];
__device__ __nv_bfloat16 g_VPh[MTOT * DD], g_VPl[MTOT * DD];
__device__ __nv_bfloat16 g_Zh[MTOT * DD], g_Zl[MTOT * DD];
__device__ __nv_bfloat16 g_Wqh[DD * DD], g_Wql[DD * DD];
__device__ __nv_bfloat16 g_Wkh[DD * DD], g_Wkl[DD * DD];
__device__ __nv_bfloat16 g_Wvh[DD * DD], g_Wvl[DD * DD];
__device__ __nv_bfloat16 g_Wph[DD * DD], g_Wpl[DD * DD];

// ---------------------------------------------------------------------------
// Portable PTX helpers (sm_80+: ldmatrix / mma.sync / cp.async)
// ---------------------------------------------------------------------------
__device__ __forceinline__ uint32_t smem_u32(const void* p) {
    uint32_t a;
    asm("{ .reg .u64 t; cvta.to.shared.u64 t, %1; cvt.u32.u64 %0, t; }"
        : "=r"(a) : "l"(p));
    return a;
}

__device__ __forceinline__ void ldsm4(uint32_t addr, uint32_t* r) {
    asm volatile("ldmatrix.sync.aligned.m8n8.x4.shared.b16 {%0,%1,%2,%3}, [%4];"
        : "=r"(r[0]), "=r"(r[1]), "=r"(r[2]), "=r"(r[3]) : "r"(addr));
}

__device__ __forceinline__ void ldsm4t(uint32_t addr, uint32_t* r) {
    asm volatile("ldmatrix.sync.aligned.m8n8.x4.trans.shared.b16 {%0,%1,%2,%3}, [%4];"
        : "=r"(r[0]), "=r"(r[1]), "=r"(r[2]), "=r"(r[3]) : "r"(addr));
}

__device__ __forceinline__ void mma16816(float* c, const uint32_t* a, const uint32_t* b) {
    asm volatile(
        "mma.sync.aligned.m16n8k16.row.col.f32.bf16.bf16.f32 "
        "{%0,%1,%2,%3}, {%4,%5,%6,%7}, {%8,%9}, {%0,%1,%2,%3};"
        : "+f"(c[0]), "+f"(c[1]), "+f"(c[2]), "+f"(c[3])
        : "r"(a[0]), "r"(a[1]), "r"(a[2]), "r"(a[3]), "r"(b[0]), "r"(b[1]));
}

__device__ __forceinline__ void cp16(uint32_t dst, const void* src) {
    asm volatile("cp.async.cg.shared.global [%0], [%1], 16;" :: "r"(dst), "l"(src));
}
#define CP_COMMIT asm volatile("cp.async.commit_group;" ::: "memory")
#define CP_WAIT1  asm volatile("cp.async.wait_group 1;" ::: "memory")
#define CP_WAIT0  asm volatile("cp.async.wait_group 0;" ::: "memory")

// pack (a,b) -> bf16x2 hi word + bf16x2 residual word
__device__ __forceinline__ void hilo2(float a, float b, uint32_t& h, uint32_t& l) {
    __nv_bfloat162 hh = __floats2bfloat162_rn(a, b);
    float ra = a - __bfloat162float(hh.x);
    float rb = b - __bfloat162float(hh.y);
    __nv_bfloat162 ll = __floats2bfloat162_rn(ra, rb);
    h = *(uint32_t*)&hh;
    l = *(uint32_t*)&ll;
}

// ---------------------------------------------------------------------------
// fp32 -> (bf16 hi, bf16 lo) split conversion.
// ---------------------------------------------------------------------------
__global__ __launch_bounds__(256)
void cvt_hilo(const float* __restrict__ x, __nv_bfloat16* __restrict__ hi,
              __nv_bfloat16* __restrict__ lo)
{
    const int i = (blockIdx.x * 256 + threadIdx.x) * 4;
    float4 v = *(const float4*)(x + i);
    float vv[4] = {v.x, v.y, v.z, v.w};
#pragma unroll
    for (int j = 0; j < 4; j++) {
        __nv_bfloat16 h = __float2bfloat16(vv[j]);
        hi[i + j] = h;
        lo[i + j] = __float2bfloat16(vv[j] - __bfloat162float(h));
    }
}

// ---------------------------------------------------------------------------
// mma.sync bf16-split GEMM: C = (Ah+Al)[M,K] x (Wh+Wl)[N,K]^T + bias
// CTA 128x128, BK=32, 2-stage cp.async, single sync per slab, 2 CTAs/SM.
// MODE 0: fp32 row-major to Cf.  MODE 1: bf16 hi/lo scatter to [b,h,s,k].
// ---------------------------------------------------------------------------
#define TILE_B (128 * 80)        // 10240 bytes per 128x32 tile (80B rows)
#define STAGE_B (4 * TILE_B)
#define SMEM_GEMM (2 * STAGE_B)  // 81920

template <int MODE>
__global__ __launch_bounds__(256, 2)
void gemm_mma(const __nv_bfloat16* __restrict__ Ah, const __nv_bfloat16* __restrict__ Al,
              const __nv_bfloat16* __restrict__ Wh, const __nv_bfloat16* __restrict__ Wl,
              const float* __restrict__ bias, float* __restrict__ Cf,
              __nv_bfloat16* __restrict__ Chi, __nv_bfloat16* __restrict__ Clo)
{
    extern __shared__ __align__(16) char smem[];
    const uint32_t sb = smem_u32(smem);

    const int tid  = threadIdx.x;
    const int lane = tid & 31;
    const int wid  = tid >> 5;
    const int wm   = wid & 1;
    const int wn   = wid >> 1;
    const int m0 = blockIdx.y * 128;
    const int n0 = blockIdx.x * 128;

    const __nv_bfloat16* src[4] = {
        Ah + (size_t)m0 * DD, Al + (size_t)m0 * DD,
        Wh + (size_t)n0 * DD, Wl + (size_t)n0 * DD };

    auto load_stage = [&](int stage, int ks) {
#pragma unroll
        for (int i = 0; i < 8; i++) {
            const int c   = tid + i * 256;
            const int t   = c >> 9;
            const int cc  = c & 511;
            const int row = cc >> 2;
            const int ch  = cc & 3;
            cp16(sb + stage * STAGE_B + t * TILE_B + row * 80 + ch * 16,
                 src[t] + (size_t)row * DD + ks * 32 + ch * 8);
        }
    };

    float acc[4][4][4];
#pragma unroll
    for (int mi = 0; mi < 4; mi++)
#pragma unroll
        for (int ni = 0; ni < 4; ni++)
#pragma unroll
            for (int j = 0; j < 4; j++) acc[mi][ni][j] = 0.0f;

    load_stage(0, 0);
    CP_COMMIT;

    for (int ks = 0; ks < 32; ks++) {
        // stage ks is the only pending group for this warp -> wait, publish.
        CP_WAIT0;
        __syncthreads();
        // all warps finished computing slab ks-1 -> buffer (ks+1)&1 is free.
        if (ks < 31) {
            load_stage((ks + 1) & 1, ks + 1);
            CP_COMMIT;
        }

        const uint32_t stb = sb + (ks & 1) * STAGE_B;
        const uint32_t sAh = stb;
        const uint32_t sAl = stb + TILE_B;
        const uint32_t sWh = stb + 2 * TILE_B;
        const uint32_t sWl = stb + 3 * TILE_B;

#pragma unroll
        for (int kk = 0; kk < 32; kk += 16) {
            uint32_t bh[4][2], bl[4][2];
#pragma unroll
            for (int np = 0; np < 2; np++) {
                const int g    = lane >> 3;
                const int brow = wn * 32 + np * 16 + ((g >> 1) << 3) + (lane & 7);
                const int bk   = kk + ((g & 1) << 3);
                uint32_t r[4];
                ldsm4(sWh + brow * 80 + bk * 2, r);
                bh[2 * np][0] = r[0]; bh[2 * np][1] = r[1];
                bh[2 * np + 1][0] = r[2]; bh[2 * np + 1][1] = r[3];
                ldsm4(sWl + brow * 80 + bk * 2, r);
                bl[2 * np][0] = r[0]; bl[2 * np][1] = r[1];
                bl[2 * np + 1][0] = r[2]; bl[2 * np + 1][1] = r[3];
            }
            const int arow_off = (lane & 15);
            const int ak = kk + ((lane >> 4) << 3);
#pragma unroll
            for (int mi = 0; mi < 4; mi++) {
                const int arow = wm * 64 + mi * 16 + arow_off;
                uint32_t ah[4], al[4];
                ldsm4(sAh + arow * 80 + ak * 2, ah);
                ldsm4(sAl + arow * 80 + ak * 2, al);
#pragma unroll
                for (int ni = 0; ni < 4; ni++) {
                    mma16816(acc[mi][ni], ah, bh[ni]);
                    mma16816(acc[mi][ni], al, bh[ni]);
                    mma16816(acc[mi][ni], ah, bl[ni]);
                }
            }
        }
    }

#pragma unroll
    for (int mi = 0; mi < 4; mi++) {
#pragma unroll
        for (int ni = 0; ni < 4; ni++) {
            const int row0 = m0 + wm * 64 + mi * 16 + (lane >> 2);
            const int col  = n0 + wn * 32 + ni * 8 + 2 * (lane & 3);
            const float b0 = __ldg(bias + col);
            const float b1 = __ldg(bias + col + 1);
            const float v00 = acc[mi][ni][0] + b0, v01 = acc[mi][ni][1] + b1;
            const float v10 = acc[mi][ni][2] + b0, v11 = acc[mi][ni][3] + b1;
            if (MODE == 0) {
                *(float2*)(Cf + (size_t)row0 * DD + col) = make_float2(v00, v01);
                *(float2*)(Cf + (size_t)(row0 + 8) * DD + col) = make_float2(v10, v11);
            } else {
                const int h = col >> 6, k = col & 63;
                uint32_t ph, pl;
                {
                    const int b = row0 >> 11, s = row0 & 2047;
                    const size_t o = (((size_t)b * HH + h) * SS + s) * DK + k;
                    hilo2(v00, v01, ph, pl);
                    *(uint32_t*)(Chi + o) = ph;
                    *(uint32_t*)(Clo + o) = pl;
                }
                {
                    const int r1 = row0 + 8;
                    const int b = r1 >> 11, s = r1 & 2047;
                    const size_t o = (((size_t)b * HH + h) * SS + s) * DK + k;
                    hilo2(v10, v11, ph, pl);
                    *(uint32_t*)(Chi + o) = ph;
                    *(uint32_t*)(Clo + o) = pl;
                }
            }
        }
    }
}

// ---------------------------------------------------------------------------
// Causal flash attention on mma.sync bf16 with hi/lo split.
// CTA = 64 q rows (4 warps x 16), K/V blocks of 64, 2-stage cp.async.
// Grid: (S/64, B*H).
// ---------------------------------------------------------------------------
#define ROWB 144                   // 64 bf16 data + 16B pad
#define KVTILE (64 * ROWB)         // 9216
#define STG (4 * KVTILE)           // Kh, Kl, Vh, Vl = 36864
#define SMEM_ATT (2 * STG)         // 73728

__global__ __launch_bounds__(128)
void attn_mma()
{
    extern __shared__ __align__(16) char smem[];
    const uint32_t sb = smem_u32(smem);
    const int tid  = threadIdx.x;
    const int lane = tid & 31;
    const int w    = tid >> 5;
    const int qb   = blockIdx.x;    // 0..31
    const int bh   = blockIdx.y;    // 0..63

    const size_t hoff = (size_t)bh * SS * DK;
    const __nv_bfloat16* kvsrc[4] = {
        g_KPh + hoff, g_KPl + hoff, g_VPh + hoff, g_VPl + hoff };

    auto load_kv = [&](int kb, int stage) {
        const size_t base = (size_t)kb * 64 * DK;
#pragma unroll
        for (int i = 0; i < 16; i++) {
            const int c   = tid + i * 128;
            const int t   = c >> 9;
            const int cc  = c & 511;
            const int row = cc >> 3;
            const int ch  = cc & 7;
            cp16(sb + stage * STG + t * KVTILE + row * ROWB + ch * 16,
                 kvsrc[t] + base + row * DK + ch * 8);
        }
    };

    // ---- prologue: Q tile (hi/lo) into buf1, KV block 0 into buf0 ----
    {
        const __nv_bfloat16* qsrc[2] = {
            g_QPh + hoff + (size_t)qb * 64 * DK,
            g_QPl + hoff + (size_t)qb * 64 * DK };
#pragma unroll
        for (int i = 0; i < 8; i++) {
            const int c   = tid + i * 128;
            const int t   = c >> 9;
            const int cc  = c & 511;
            const int row = cc >> 3;
            const int ch  = cc & 7;
            cp16(sb + STG + t * KVTILE + row * ROWB + ch * 16,
                 qsrc[t] + row * DK + ch * 8);
        }
    }
    CP_COMMIT;
    load_kv(0, 0);
    CP_COMMIT;
    CP_WAIT1;                      // Q done
    __syncthreads();

    uint32_t qfh[4][4], qfl[4][4];
#pragma unroll
    for (int kc = 0; kc < 4; kc++) {
        const int row = w * 16 + (lane & 15);
        const int k   = kc * 16 + ((lane >> 4) << 3);
        ldsm4(sb + STG + row * ROWB + k * 2, qfh[kc]);
        ldsm4(sb + STG + KVTILE + row * ROWB + k * 2, qfl[kc]);
    }
    __syncthreads();               // Q frags read before buf1 reuse

    float co[8][4];
#pragma unroll
    for (int n = 0; n < 8; n++)
#pragma unroll
        for (int j = 0; j < 4; j++) co[n][j] = 0.0f;
    float m0v = -1e30f, m1v = -1e30f, l0 = 0.0f, l1 = 0.0f;

    for (int kb = 0; kb <= qb; kb++) {
        CP_WAIT0;
        __syncthreads();
        if (kb < qb) {
            load_kv(kb + 1, (kb + 1) & 1);
            CP_COMMIT;
        }

        const uint32_t stb = sb + (kb & 1) * STG;

        // ---- S = Q K^T (3 split products), fp32 acc ----
        float c[8][4];
#pragma unroll
        for (int n = 0; n < 8; n++)
#pragma unroll
            for (int j = 0; j < 4; j++) c[n][j] = 0.0f;

#pragma unroll
        for (int kc = 0; kc < 4; kc++) {
            uint32_t kfh[8][2], kfl[8][2];
#pragma unroll
            for (int p = 0; p < 4; p++) {
                const int g    = lane >> 3;
                const int brow = p * 16 + ((g >> 1) << 3) + (lane & 7);
                const int bk   = kc * 16 + ((g & 1) << 3);
                uint32_t r[4];
                ldsm4(stb + brow * ROWB + bk * 2, r);
                kfh[2 * p][0] = r[0]; kfh[2 * p][1] = r[1];
                kfh[2 * p + 1][0] = r[2]; kfh[2 * p + 1][1] = r[3];
                ldsm4(stb + KVTILE + brow * ROWB + bk * 2, r);
                kfl[2 * p][0] = r[0]; kfl[2 * p][1] = r[1];
                kfl[2 * p + 1][0] = r[2]; kfl[2 * p + 1][1] = r[3];
            }
#pragma unroll
            for (int n = 0; n < 8; n++) {
                mma16816(c[n], qfh[kc], kfh[n]);
                mma16816(c[n], qfl[kc], kfh[n]);
                mma16816(c[n], qfh[kc], kfl[n]);
            }
        }

        // ---- softmax (scale 1/8, causal mask on diagonal block) ----
        const bool diag = (kb == qb);
        const int r0 = lane >> 2, r1 = r0 + 8;
        const int rowloc = w * 16;
        float mx0 = -1e30f, mx1 = -1e30f;
#pragma unroll
        for (int n = 0; n < 8; n++) {
#pragma unroll
            for (int j = 0; j < 4; j++) {
                c[n][j] *= 0.125f;
                if (diag) {
                    const int col = n * 8 + 2 * (lane & 3) + (j & 1);
                    const int row = rowloc + ((j < 2) ? r0 : r1);
                    if (col > row) c[n][j] = -1e30f;
                }
            }
            mx0 = fmaxf(mx0, fmaxf(c[n][0], c[n][1]));
            mx1 = fmaxf(mx1, fmaxf(c[n][2], c[n][3]));
        }
        mx0 = fmaxf(mx0, __shfl_xor_sync(0xffffffff, mx0, 1));
        mx0 = fmaxf(mx0, __shfl_xor_sync(0xffffffff, mx0, 2));
        mx1 = fmaxf(mx1, __shfl_xor_sync(0xffffffff, mx1, 1));
        mx1 = fmaxf(mx1, __shfl_xor_sync(0xffffffff, mx1, 2));

        const float mn0 = fmaxf(m0v, mx0), mn1 = fmaxf(m1v, mx1);
        const float cor0 = __expf(m0v - mn0), cor1 = __expf(m1v - mn1);
        m0v = mn0; m1v = mn1;

        float s0 = 0.0f, s1 = 0.0f;
#pragma unroll
        for (int n = 0; n < 8; n++) {
            c[n][0] = __expf(c[n][0] - mn0);
            c[n][1] = __expf(c[n][1] - mn0);
            c[n][2] = __expf(c[n][2] - mn1);
            c[n][3] = __expf(c[n][3] - mn1);
            s0 += c[n][0] + c[n][1];
            s1 += c[n][2] + c[n][3];
        }
        s0 += __shfl_xor_sync(0xffffffff, s0, 1);
        s0 += __shfl_xor_sync(0xffffffff, s0, 2);
        s1 += __shfl_xor_sync(0xffffffff, s1, 1);
        s1 += __shfl_xor_sync(0xffffffff, s1, 2);
        l0 = l0 * cor0 + s0;
        l1 = l1 * cor1 + s1;
#pragma unroll
        for (int n = 0; n < 8; n++) {
            co[n][0] *= cor0; co[n][1] *= cor0;
            co[n][2] *= cor1; co[n][3] *= cor1;
        }

        // ---- pack P as bf16 hi/lo A-fragments ----
        uint32_t pah[4][4], pal[4][4];
#pragma unroll
        for (int kc = 0; kc < 4; kc++) {
            hilo2(c[2 * kc][0],     c[2 * kc][1],     pah[kc][0], pal[kc][0]);
            hilo2(c[2 * kc][2],     c[2 * kc][3],     pah[kc][1], pal[kc][1]);
            hilo2(c[2 * kc + 1][0], c[2 * kc + 1][1], pah[kc][2], pal[kc][2]);
            hilo2(c[2 * kc + 1][2], c[2 * kc + 1][3], pah[kc][3], pal[kc][3]);
        }

        // ---- O += P V (3 split products); V via ldmatrix.trans ----
#pragma unroll
        for (int kc = 0; kc < 4; kc++) {
            uint32_t vfh[8][2], vfl[8][2];
#pragma unroll
            for (int dp = 0; dp < 4; dp++) {
                const int g    = lane >> 3;
                const int j    = lane & 7;
                const int srow = kc * 16 + ((g & 1) << 3) + j;
                const int dcol = dp * 16 + ((g >> 1) << 3);
                uint32_t r[4];
                ldsm4t(stb + 2 * KVTILE + srow * ROWB + dcol * 2, r);
                vfh[2 * dp][0] = r[0]; vfh[2 * dp][1] = r[1];
                vfh[2 * dp + 1][0] = r[2]; vfh[2 * dp + 1][1] = r[3];
                ldsm4t(stb + 3 * KVTILE + srow * ROWB + dcol * 2, r);
                vfl[2 * dp][0] = r[0]; vfl[2 * dp][1] = r[1];
                vfl[2 * dp + 1][0] = r[2]; vfl[2 * dp + 1][1] = r[3];
            }
#pragma unroll
            for (int n = 0; n < 8; n++) {
                mma16816(co[n], pah[kc], vfh[n]);
                mma16816(co[n], pal[kc], vfh[n]);
                mma16816(co[n], pah[kc], vfl[n]);
            }
        }
    }

    // ---- epilogue: O /= l, write concat-heads bf16 hi/lo ----
    const float i0 = 1.0f / l0, i1 = 1.0f / l1;
    const int b  = bh >> 4;
    const int hh = bh & 15;
    const int q0 = qb * 64 + w * 16 + (lane >> 2);
#pragma unroll
    for (int n = 0; n < 8; n++) {
        const int dk = n * 8 + 2 * (lane & 3);
        const size_t o0 = ((size_t)b * SS + q0) * DD + hh * 64 + dk;
        const size_t o1 = o0 + (size_t)8 * DD;
        uint32_t ph, pl;
        hilo2(co[n][0] * i0, co[n][1] * i0, ph, pl);
        *(uint32_t*)(g_Zh + o0) = ph;
        *(uint32_t*)(g_Zl + o0) = pl;
        hilo2(co[n][2] * i1, co[n][3] * i1, ph, pl);
        *(uint32_t*)(g_Zh + o1) = ph;
        *(uint32_t*)(g_Zl + o1) = pl;
    }
}

// ---------------------------------------------------------------------------
// Launch
// ---------------------------------------------------------------------------
extern "C" void kernel_launch(void* const* d_in, const int* in_sizes, int n_in,
                              void* d_out, int out_size)
{
    const float* query = (const float*)d_in[0];
    const float* key   = (const float*)d_in[1];
    const float* value = (const float*)d_in[2];
    const float* Wq    = (const float*)d_in[3];
    const float* bq    = (const float*)d_in[4];
    const float* Wk    = (const float*)d_in[5];
    const float* bk    = (const float*)d_in[6];
    const float* Wv    = (const float*)d_in[7];
    const float* bv    = (const float*)d_in[8];
    const float* Wp    = (const float*)d_in[9];
    const float* bp    = (const float*)d_in[10];
    // d_in[11] = mask (statically causal -> applied analytically)

    __nv_bfloat16 *qh, *ql, *kh, *kl, *vh, *vl;
    __nv_bfloat16 *QPh, *QPl, *KPh, *KPl, *VPh, *VPl, *Zh, *Zl;
    __nv_bfloat16 *Wqh, *Wql, *Wkh, *Wkl, *Wvh, *Wvl, *Wph, *Wpl;
    cudaGetSymbolAddress((void**)&qh, g_qh);   cudaGetSymbolAddress((void**)&ql, g_ql);
    cudaGetSymbolAddress((void**)&kh, g_kh);   cudaGetSymbolAddress((void**)&kl, g_kl);
    cudaGetSymbolAddress((void**)&vh, g_vh);   cudaGetSymbolAddress((void**)&vl, g_vl);
    cudaGetSymbolAddress((void**)&QPh, g_QPh); cudaGetSymbolAddress((void**)&QPl, g_QPl);
    cudaGetSymbolAddress((void**)&KPh, g_KPh); cudaGetSymbolAddress((void**)&KPl, g_KPl);
    cudaGetSymbolAddress((void**)&VPh, g_VPh); cudaGetSymbolAddress((void**)&VPl, g_VPl);
    cudaGetSymbolAddress((void**)&Zh, g_Zh);   cudaGetSymbolAddress((void**)&Zl, g_Zl);
    cudaGetSymbolAddress((void**)&Wqh, g_Wqh); cudaGetSymbolAddress((void**)&Wql, g_Wql);
    cudaGetSymbolAddress((void**)&Wkh, g_Wkh); cudaGetSymbolAddress((void**)&Wkl, g_Wkl);
    cudaGetSymbolAddress((void**)&Wvh, g_Wvh); cudaGetSymbolAddress((void**)&Wvl, g_Wvl);
    cudaGetSymbolAddress((void**)&Wph, g_Wph); cudaGetSymbolAddress((void**)&Wpl, g_Wpl);

    cudaFuncSetAttribute(gemm_mma<0>, cudaFuncAttributeMaxDynamicSharedMemorySize, SMEM_GEMM);
    cudaFuncSetAttribute(gemm_mma<1>, cudaFuncAttributeMaxDynamicSharedMemorySize, SMEM_GEMM);
    cudaFuncSetAttribute(attn_mma, cudaFuncAttributeMaxDynamicSharedMemorySize, SMEM_ATT);

    cvt_hilo<<<MTOT * DD / 1024, 256>>>(query, qh, ql);
    cvt_hilo<<<MTOT * DD / 1024, 256>>>(key,   kh, kl);
    cvt_hilo<<<MTOT * DD / 1024, 256>>>(value, vh, vl);
    cvt_hilo<<<DD * DD / 1024, 256>>>(Wq, Wqh, Wql);
    cvt_hilo<<<DD * DD / 1024, 256>>>(Wk, Wkh, Wkl);
    cvt_hilo<<<DD * DD / 1024, 256>>>(Wv, Wvh, Wvl);
    cvt_hilo<<<DD * DD / 1024, 256>>>(Wp, Wph, Wpl);

    const dim3 gg(DD / 128, MTOT / 128);   // (8, 64)

    gemm_mma<1><<<gg, 256, SMEM_GEMM>>>(qh, ql, Wqh, Wql, bq, nullptr, QPh, QPl);
    gemm_mma<1><<<gg, 256, SMEM_GEMM>>>(kh, kl, Wkh, Wkl, bk, nullptr, KPh, KPl);
    gemm_mma<1><<<gg, 256, SMEM_GEMM>>>(vh, vl, Wvh, Wvl, bv, nullptr, VPh, VPl);

    attn_mma<<<dim3(SS / 64, BB * HH), 128, SMEM_ATT>>>();

    gemm_mma<0><<<gg, 256, SMEM_GEMM>>>(Zh, Zl, Wph, Wpl, bp, (float*)d_out, nullptr, nullptr);
}